// round 13
// baseline (speedup 1.0000x reference)
#include <cuda_runtime.h>
#include <cuda_fp16.h>
#include <math.h>
#include <stdint.h>

// Problem constants
#define Bc   16
#define Sc   512
#define Vc   512
#define Hc   1024
#define NLc  8
#define NHc  16
#define DHc  64
#define Fc   4096
#define Mrows (Bc*Sc)   // 8192 token rows

// per-layer transposed-weight block offsets (element counts)
#define oQKV_ 0
#define oWO_  (3*Hc*Hc)
#define oFC_  (oWO_ + Hc*Hc)
#define oPRJ_ (oFC_ + Hc*Fc)
#define LWT   ((size_t)(oPRJ_ + Fc*Hc))

// ---------------- scratch (static device memory; no runtime allocs) ----------------
__device__ float  g_x   [(size_t)Mrows*Hc];        // residual stream (fp32)
__device__ __half g_h   [(size_t)Mrows*Hc];        // LN output (half)
__device__ __half g_qkvh[(size_t)Mrows*3*Hc];      // fused qkv (half)
__device__ __half g_attn[(size_t)Mrows*Hc];        // attention out (half)
__device__ __half g_ffn [(size_t)Mrows*Fc];        // ffn intermediate (half)
__device__ __half g_wT  [(size_t)NLc * LWT];       // transposed half weights
__device__ __half g_embH[(size_t)Vc*Hc];           // half emb ([V,H] == [N,K] for logits)

// ---------------- helpers ----------------
__device__ __forceinline__ float gelu_f(float x) {
    // tanh-approx gelu, with tanh(u) = 1 - 2/(e^{2u}+1) via fast exp (err ~1e-7)
    float u = 0.7978845608028654f * (x + 0.044715f * x * x * x);
    float t = 1.0f - 2.0f / (__expf(2.0f * u) + 1.0f);
    return 0.5f * x * (1.0f + t);
}
__device__ __forceinline__ void cp16(uint32_t saddr, const void* gptr) {
    asm volatile("cp.async.cg.shared.global [%0], [%1], 16;\n" :: "r"(saddr), "l"(gptr));
}
#define CP_COMMIT() asm volatile("cp.async.commit_group;\n" ::: "memory")
#define CP_WAIT1()  asm volatile("cp.async.wait_group 1;\n" ::: "memory")
#define CP_WAIT0()  asm volatile("cp.async.wait_group 0;\n" ::: "memory")

__device__ __forceinline__ void ldm_x4(uint32_t r[4], uint32_t addr) {
    asm volatile("ldmatrix.sync.aligned.m8n8.x4.shared.b16 {%0,%1,%2,%3}, [%4];"
                 : "=r"(r[0]), "=r"(r[1]), "=r"(r[2]), "=r"(r[3]) : "r"(addr));
}
__device__ __forceinline__ void ldm_x4_t(uint32_t r[4], uint32_t addr) {
    asm volatile("ldmatrix.sync.aligned.m8n8.x4.trans.shared.b16 {%0,%1,%2,%3}, [%4];"
                 : "=r"(r[0]), "=r"(r[1]), "=r"(r[2]), "=r"(r[3]) : "r"(addr));
}
__device__ __forceinline__ void mma_f16(float c[4], const uint32_t a[4],
                                        uint32_t b0, uint32_t b1) {
    asm volatile(
        "mma.sync.aligned.m16n8k16.row.col.f32.f16.f16.f32 "
        "{%0,%1,%2,%3}, {%4,%5,%6,%7}, {%8,%9}, {%0,%1,%2,%3};"
        : "+f"(c[0]), "+f"(c[1]), "+f"(c[2]), "+f"(c[3])
        : "r"(a[0]), "r"(a[1]), "r"(a[2]), "r"(a[3]), "r"(b0), "r"(b1));
}
__device__ __forceinline__ uint32_t pack_h2(float a, float b) {
    __half2 h = __floats2half2_rn(a, b);
    return *(uint32_t*)&h;
}

// ---------------- batched prep: all weight transposes in ONE launch ----------------
// per layer: qkv 3072 tiles | wo 1024 | wfc 4096 | wproj 4096  => 12288/layer
__global__ void prep_weights(const float* __restrict__ Wqkv, const float* __restrict__ Wo,
                             const float* __restrict__ Wfc,  const float* __restrict__ Wproj,
                             __half* __restrict__ wT) {
    __shared__ float t[32][33];
    int bid = blockIdx.x;
    int l = bid / 12288;
    int r = bid % 12288;
    __half* base = wT + (size_t)l * LWT;
    const float* in; __half* outp; int K, N, tn, tk;
    if (r < 3072) {
        in = Wqkv + (size_t)l*Hc*3*Hc; outp = base + oQKV_; K = Hc; N = 3*Hc;
        tn = r % 96; tk = r / 96;
    } else if (r < 4096) {
        int q = r - 3072;
        in = Wo + (size_t)l*Hc*Hc; outp = base + oWO_; K = Hc; N = Hc;
        tn = q % 32; tk = q / 32;
    } else if (r < 8192) {
        int q = r - 4096;
        in = Wfc + (size_t)l*Hc*Fc; outp = base + oFC_; K = Hc; N = Fc;
        tn = q % 128; tk = q / 128;
    } else {
        int q = r - 8192;
        in = Wproj + (size_t)l*Fc*Hc; outp = base + oPRJ_; K = Fc; N = Hc;
        tn = q % 32; tk = q / 32;
    }
    int n0 = tn * 32, k0 = tk * 32;
    int tx = threadIdx.x, ty = threadIdx.y;  // (32,8)
    #pragma unroll
    for (int rr = 0; rr < 32; rr += 8)
        t[ty + rr][tx] = in[(size_t)(k0 + ty + rr) * N + n0 + tx];
    __syncthreads();
    #pragma unroll
    for (int rr = 0; rr < 32; rr += 8)
        outp[(size_t)(n0 + ty + rr) * K + k0 + tx] = __float2half_rn(t[tx][ty + rr]);
}

// embH copy (blocks 0..511) + embedding gather (blocks 512..8703)
__global__ void prep_misc(const float* __restrict__ emb, __half* __restrict__ embH,
                          const int* __restrict__ ids, float* __restrict__ x) {
    int bid = blockIdx.x;
    if (bid < 512) {
        int i = bid * 256 + threadIdx.x;   // float4 index; 512*256 = 131072 = Vc*Hc/4
        float4 v = ((const float4*)emb)[i];
        ((__half2*)embH)[2*i]   = __floats2half2_rn(v.x, v.y);
        ((__half2*)embH)[2*i+1] = __floats2half2_rn(v.z, v.w);
    } else {
        int t = bid - 512;
        int id = ids[t];
        const float4* src = (const float4*)(emb + (size_t)id * Hc);
        float4* dst = (float4*)(x + (size_t)t * Hc);
        dst[threadIdx.x] = src[threadIdx.x];
    }
}

// ---------------- layernorm (half output), warp-shuffle reduce, 1 barrier ----------
__global__ void ln_kernel(const float* __restrict__ x,
                          const float* __restrict__ g,
                          const float* __restrict__ b,
                          __half* __restrict__ out) {
    __shared__ float ws[8], wq[8];
    int row = blockIdx.x, tid = threadIdx.x;
    int lane = tid & 31, w = tid >> 5;
    float4 v = ((const float4*)(x + (size_t)row * Hc))[tid];
    float s = v.x + v.y + v.z + v.w;
    float q = v.x*v.x + v.y*v.y + v.z*v.z + v.w*v.w;
    #pragma unroll
    for (int o = 16; o; o >>= 1) {
        s += __shfl_xor_sync(0xffffffffu, s, o);
        q += __shfl_xor_sync(0xffffffffu, q, o);
    }
    if (lane == 0) { ws[w] = s; wq[w] = q; }
    __syncthreads();
    s = ws[lane & 7]; q = wq[lane & 7];
    #pragma unroll
    for (int o = 4; o; o >>= 1) {
        s += __shfl_xor_sync(0xffffffffu, s, o);
        q += __shfl_xor_sync(0xffffffffu, q, o);
    }
    float mu  = s * (1.0f / Hc);
    float var = q * (1.0f / Hc) - mu * mu;
    float inv = rsqrtf(var + 1e-5f);
    float4 gg = ((const float4*)g)[tid];
    float4 bb = ((const float4*)b)[tid];
    __half2* op = (__half2*)(out + (size_t)row * Hc);
    op[2*tid]   = __floats2half2_rn((v.x - mu) * inv * gg.x + bb.x,
                                    (v.y - mu) * inv * gg.y + bb.y);
    op[2*tid+1] = __floats2half2_rn((v.z - mu) * inv * gg.z + bb.z,
                                    (v.w - mu) * inv * gg.w + bb.w);
}

// ---------------- fp16 tensor-core GEMM: C = act(A@Wt^T + bias) (+= residual C) ------
// R10-proven mainloop (frozen): 3-stage cp.async (96KB), single barrier per K-iter.
// 1D grid + tile loop (grid == nTiles in practice -> single pass).
template<bool RES, bool GELU_ACT, bool BIAS, bool OUT_HALF>
__global__ __launch_bounds__(256, 2)
void gemm_h(const __half* __restrict__ A, const __half* __restrict__ Wt,
            const float* __restrict__ bias, void* __restrict__ Cv,
            int N, int K, int nNt, int nTiles) {
    extern __shared__ uint8_t dsm[];
    uint32_t smem = (uint32_t)__cvta_generic_to_shared(dsm);
    const uint32_t sA = smem;            // 3 stages x 16KB
    const uint32_t sB = smem + 49152;    // 3 stages x 16KB

    int tid = threadIdx.x, wid = tid >> 5, lane = tid & 31;
    int warpM = (wid >> 2) * 64;
    int warpN = (wid & 3) * 32;
    int nIter = K >> 6;

    int row = tid >> 1;
    int hseg = (tid & 1) * 32;
    uint32_t so[4];
    #pragma unroll
    for (int i = 0; i < 4; ++i) {
        int c = (tid & 1) * 4 + i;
        so[i] = row * 128 + ((c ^ (row & 7)) << 4);
    }
    int lrow = lane & 15;
    int lchk = lane >> 4;

    for (int t = blockIdx.x; t < nTiles; t += gridDim.x) {
        if (t != (int)blockIdx.x) __syncthreads();   // prior tile's smem reads done
        int m0 = (t / nNt) * 128, n0 = (t % nNt) * 128;

        float acc[4][4][4];
        #pragma unroll
        for (int i = 0; i < 4; ++i)
            #pragma unroll
            for (int j = 0; j < 4; ++j)
                #pragma unroll
                for (int r = 0; r < 4; ++r) acc[i][j][r] = 0.f;

        const __half* ag = A  + (size_t)(m0 + row) * K + hseg;
        const __half* bg = Wt + (size_t)(n0 + row) * K + hseg;

        auto prefetch = [&](int it) {
            if (it < nIter) {
                uint32_t a_st = sA + (it % 3) * 16384;
                uint32_t b_st = sB + (it % 3) * 16384;
                const __half* ap = ag + (size_t)it * 64;
                const __half* bp = bg + (size_t)it * 64;
                #pragma unroll
                for (int i = 0; i < 4; ++i) cp16(a_st + so[i], ap + 8 * i);
                #pragma unroll
                for (int i = 0; i < 4; ++i) cp16(b_st + so[i], bp + 8 * i);
            }
            CP_COMMIT();
        };

        prefetch(0);
        prefetch(1);

        for (int it = 0; it < nIter; ++it) {
            CP_WAIT1();
            __syncthreads();
            prefetch(it + 2);     // stage (it-1)%3 — free after the barrier
            uint32_t aBase = sA + (it % 3) * 16384;
            uint32_t bBase = sB + (it % 3) * 16384;
            #pragma unroll
            for (int ks = 0; ks < 4; ++ks) {
                uint32_t af[4][4], bf[2][4];
                int c = ks * 2 + lchk;
                #pragma unroll
                for (int mf = 0; mf < 4; ++mf) {
                    int r = warpM + mf * 16 + lrow;
                    ldm_x4(af[mf], aBase + r * 128 + ((c ^ (r & 7)) << 4));
                }
                #pragma unroll
                for (int g = 0; g < 2; ++g) {
                    int r = warpN + g * 16 + lrow;
                    ldm_x4(bf[g], bBase + r * 128 + ((c ^ (r & 7)) << 4));
                }
                #pragma unroll
                for (int mf = 0; mf < 4; ++mf) {
                    mma_f16(acc[mf][0], af[mf], bf[0][0], bf[0][2]);
                    mma_f16(acc[mf][1], af[mf], bf[0][1], bf[0][3]);
                    mma_f16(acc[mf][2], af[mf], bf[1][0], bf[1][2]);
                    mma_f16(acc[mf][3], af[mf], bf[1][1], bf[1][3]);
                }
            }
        }

        int rbase = m0 + warpM + (lane >> 2);
        int cbase = n0 + warpN + (lane & 3) * 2;
        #pragma unroll
        for (int mf = 0; mf < 4; ++mf) {
            #pragma unroll
            for (int nf = 0; nf < 4; ++nf) {
                int c = cbase + nf * 8;
                float bx = 0.f, by = 0.f;
                if (BIAS) { bx = bias[c]; by = bias[c + 1]; }
                #pragma unroll
                for (int half_ = 0; half_ < 2; ++half_) {
                    int r = rbase + mf * 16 + half_ * 8;
                    float v0 = acc[mf][nf][half_ * 2 + 0] + bx;
                    float v1 = acc[mf][nf][half_ * 2 + 1] + by;
                    if (GELU_ACT) { v0 = gelu_f(v0); v1 = gelu_f(v1); }
                    if (OUT_HALF) {
                        __half2* cp = (__half2*)((__half*)Cv + (size_t)r * N + c);
                        *cp = __floats2half2_rn(v0, v1);
                    } else {
                        float2* cp = (float2*)((float*)Cv + (size_t)r * N + c);
                        if (RES) { float2 old = *cp; v0 += old.x; v1 += old.y; }
                        float2 o; o.x = v0; o.y = v1;
                        *cp = o;
                    }
                }
            }
        }
    }
}

// ---------------- fused flash attention ----------------
// grid: (S/128, B*NH); 256 threads (8 warps x 16 rows). K/V 64-row tiles,
// double buffered, single barrier per j-tile, split-mask tile skipping.
// NEW: heavy-first (LPT) CTA ordering — blockIdx.x 0 maps to the LAST i-tile
// (most j-tiles), so the heaviest CTAs launch in wave 1 and the tail shrinks.
__global__ __launch_bounds__(256)
void flash_kernel(const __half* __restrict__ qkvh, const int* __restrict__ sp,
                  __half* __restrict__ out) {
    __shared__ __align__(128) uint8_t sm[49152];
    uint32_t S0 = (uint32_t)__cvta_generic_to_shared(sm);
    const uint32_t sQ = S0;
    int tid = threadIdx.x, w = tid >> 5, lane = tid & 31;
    int ixt = gridDim.x - 1 - blockIdx.x;       // heavy-first remap
    int i0 = ixt * 128;
    int bz = blockIdx.y;
    int b = bz >> 4, n = bz & 15;
    int spb = sp[b];
    float slope = exp2f(-0.5f * (float)(n + 1));

    const __half* qbase = qkvh + (size_t)b * Sc * 3 * Hc + n * 64;

    int jstart = (spb <= i0) ? (spb >> 6) : 0;

    // Q tile 128x64 -> smem (group 0, together with KV tile jstart)
    #pragma unroll
    for (int itr = 0; itr < 4; ++itr) {
        int id = itr * 256 + tid;
        int row = id >> 3, ch = id & 7;
        cp16(sQ + row * 128 + ((ch ^ (row & 7)) << 4),
             qbase + (size_t)(i0 + row) * 3 * Hc + ch * 8);
    }
    auto prefKV = [&](int jt) {
        int stage = jt & 1;
        uint32_t sK = S0 + 16384 + stage * 16384;
        uint32_t sV = sK + 8192;
        int j0 = jt * 64;
        #pragma unroll
        for (int itr = 0; itr < 2; ++itr) {
            int id = itr * 256 + tid;
            int row = id >> 3, ch = id & 7;
            uint32_t sw = row * 128 + ((ch ^ (row & 7)) << 4);
            const __half* g = qbase + (size_t)(j0 + row) * 3 * Hc + ch * 8;
            cp16(sK + sw, g + Hc);
            cp16(sV + sw, g + 2 * Hc);
        }
    };
    prefKV(jstart);
    CP_COMMIT();

    int jtmax = ixt * 2 + 1;
    int ibase = i0 + w * 16;
    int irow = ibase + (lane >> 2);
    int jcl = (lane & 3) * 2;

    float m_run[2] = {-1e30f, -1e30f};
    float l[2] = {0.f, 0.f};
    float co[8][4];
    #pragma unroll
    for (int i = 0; i < 8; ++i)
        #pragma unroll
        for (int j = 0; j < 4; ++j) co[i][j] = 0.f;
    uint32_t aq[4][4];
    bool qLoaded = false;

    for (int jt = jstart; jt <= jtmax; ++jt) {
        CP_WAIT0();           // stage jt (and everything earlier) resident
        __syncthreads();      // all warps done with compute(jt-1); stage (jt+1)&1 free
        if (jt < jtmax) { prefKV(jt + 1); CP_COMMIT(); }
        int stage = jt & 1;
        uint32_t sK = S0 + 16384 + stage * 16384;
        uint32_t sV = sK + 8192;
        if (!qLoaded) {
            qLoaded = true;
            #pragma unroll
            for (int kc = 0; kc < 4; ++kc) {
                int r = w * 16 + (lane & 15);
                int c = kc * 2 + (lane >> 4);
                ldm_x4(aq[kc], sQ + r * 128 + ((c ^ (r & 7)) << 4));
            }
        }
        int j0 = jt * 64;
        if (j0 <= ibase + 15) {
            float c[8][4];
            #pragma unroll
            for (int i = 0; i < 8; ++i)
                #pragma unroll
                for (int j = 0; j < 4; ++j) c[i][j] = 0.f;
            // S = Q K^T
            #pragma unroll
            for (int kc = 0; kc < 4; ++kc) {
                uint32_t bf[4][4];
                #pragma unroll
                for (int g = 0; g < 4; ++g) {
                    int r = g * 16 + (lane & 15);
                    int cc = kc * 2 + (lane >> 4);
                    ldm_x4(bf[g], sK + r * 128 + ((cc ^ (r & 7)) << 4));
                }
                #pragma unroll
                for (int g = 0; g < 4; ++g) {
                    mma_f16(c[g * 2],     aq[kc], bf[g][0], bf[g][2]);
                    mma_f16(c[g * 2 + 1], aq[kc], bf[g][1], bf[g][3]);
                }
            }
            // mask + alibi
            float tmax[2] = {-1e30f, -1e30f};
            #pragma unroll
            for (int nf = 0; nf < 8; ++nf)
                #pragma unroll
                for (int rg = 0; rg < 4; ++rg) {
                    int i = irow + (rg >> 1) * 8;
                    int j = j0 + nf * 8 + jcl + (rg & 1);
                    bool ok = (j <= i) && !((i >= spb) && (j < spb));
                    float v = ok ? fmaf(c[nf][rg], 0.125f, -slope * (float)(i - j))
                                 : -1e9f;
                    c[nf][rg] = v;
                    tmax[rg >> 1] = fmaxf(tmax[rg >> 1], v);
                }
            float sfv[2];
            #pragma unroll
            for (int h = 0; h < 2; ++h) {
                tmax[h] = fmaxf(tmax[h], __shfl_xor_sync(0xffffffffu, tmax[h], 1));
                tmax[h] = fmaxf(tmax[h], __shfl_xor_sync(0xffffffffu, tmax[h], 2));
                float mn = fmaxf(m_run[h], tmax[h]);
                sfv[h] = __expf(m_run[h] - mn);
                m_run[h] = mn;
            }
            float rs[2] = {0.f, 0.f};
            #pragma unroll
            for (int nf = 0; nf < 8; ++nf)
                #pragma unroll
                for (int rg = 0; rg < 4; ++rg) {
                    float p = __expf(c[nf][rg] - m_run[rg >> 1]);
                    c[nf][rg] = p;
                    rs[rg >> 1] += p;
                }
            #pragma unroll
            for (int h = 0; h < 2; ++h) {
                rs[h] += __shfl_xor_sync(0xffffffffu, rs[h], 1);
                rs[h] += __shfl_xor_sync(0xffffffffu, rs[h], 2);
                l[h] = l[h] * sfv[h] + rs[h];
            }
            #pragma unroll
            for (int nf = 0; nf < 8; ++nf)
                #pragma unroll
                for (int rg = 0; rg < 4; ++rg) co[nf][rg] *= sfv[rg >> 1];
            // P fragments (register reshuffle)
            uint32_t ap[4][4];
            #pragma unroll
            for (int kc = 0; kc < 4; ++kc) {
                ap[kc][0] = pack_h2(c[2*kc][0],   c[2*kc][1]);
                ap[kc][1] = pack_h2(c[2*kc][2],   c[2*kc][3]);
                ap[kc][2] = pack_h2(c[2*kc+1][0], c[2*kc+1][1]);
                ap[kc][3] = pack_h2(c[2*kc+1][2], c[2*kc+1][3]);
            }
            // O += P V
            #pragma unroll
            for (int kc = 0; kc < 4; ++kc) {
                #pragma unroll
                for (int dp = 0; dp < 4; ++dp) {
                    uint32_t vf[4];
                    int r = kc * 16 + (lane & 15);
                    int cc = dp * 2 + (lane >> 4);
                    ldm_x4_t(vf, sV + r * 128 + ((cc ^ (r & 7)) << 4));
                    mma_f16(co[dp * 2],     ap[kc], vf[0], vf[1]);
                    mma_f16(co[dp * 2 + 1], ap[kc], vf[2], vf[3]);
                }
            }
        }
    }

    float inv0 = 1.0f / l[0], inv1 = 1.0f / l[1];
    #pragma unroll
    for (int nf = 0; nf < 8; ++nf) {
        int cidx = n * 64 + nf * 8 + jcl;
        __half2* o0 = (__half2*)&out[(size_t)(b * Sc + irow) * Hc + cidx];
        *o0 = __floats2half2_rn(co[nf][0] * inv0, co[nf][1] * inv0);
        __half2* o1 = (__half2*)&out[(size_t)(b * Sc + irow + 8) * Hc + cidx];
        *o1 = __floats2half2_rn(co[nf][2] * inv1, co[nf][3] * inv1);
    }
}

// ---------------- launch ----------------
#define GEMM_SMEM 98304

extern "C" void kernel_launch(void* const* d_in, const int* in_sizes, int n_in,
                              void* d_out, int out_size) {
    const int*   ids    = (const int*)d_in[0];
    const int*   sp     = (const int*)d_in[1];
    const float* emb    = (const float*)d_in[2];
    const float* ln1_g  = (const float*)d_in[3];
    const float* ln1_b  = (const float*)d_in[4];
    const float* Wqkv   = (const float*)d_in[5];
    const float* bqkv   = (const float*)d_in[6];
    const float* Wo     = (const float*)d_in[7];
    const float* bo     = (const float*)d_in[8];
    const float* ln2_g  = (const float*)d_in[9];
    const float* ln2_b  = (const float*)d_in[10];
    const float* Wfc    = (const float*)d_in[11];
    const float* bfc    = (const float*)d_in[12];
    const float* Wproj  = (const float*)d_in[13];
    const float* bproj  = (const float*)d_in[14];
    const float* lnf_g  = (const float*)d_in[15];
    const float* lnf_b  = (const float*)d_in[16];
    float* out = (float*)d_out;

    float *x;
    __half *h, *qkvh, *attn, *ffn, *wT, *embH;
    cudaGetSymbolAddress((void**)&x,    g_x);
    cudaGetSymbolAddress((void**)&h,    g_h);
    cudaGetSymbolAddress((void**)&qkvh, g_qkvh);
    cudaGetSymbolAddress((void**)&attn, g_attn);
    cudaGetSymbolAddress((void**)&ffn,  g_ffn);
    cudaGetSymbolAddress((void**)&wT,   g_wT);
    cudaGetSymbolAddress((void**)&embH, g_embH);

    cudaFuncSetAttribute(gemm_h<false,false,true,true>,
                         cudaFuncAttributeMaxDynamicSharedMemorySize, GEMM_SMEM);
    cudaFuncSetAttribute(gemm_h<true,false,true,false>,
                         cudaFuncAttributeMaxDynamicSharedMemorySize, GEMM_SMEM);
    cudaFuncSetAttribute(gemm_h<false,true,true,true>,
                         cudaFuncAttributeMaxDynamicSharedMemorySize, GEMM_SMEM);
    cudaFuncSetAttribute(gemm_h<false,false,false,false>,
                         cudaFuncAttributeMaxDynamicSharedMemorySize, GEMM_SMEM);

    prep_weights<<<NLc * 12288, dim3(32, 8)>>>(Wqkv, Wo, Wfc, Wproj, wT);
    prep_misc<<<512 + Mrows, 256>>>(emb, embH, ids, x);

    const int qkvTiles = (3*Hc/128) * (Mrows/128);     // 1536
    const int fcTiles  = (Fc/128) * (Mrows/128);       // 2048

    for (int l = 0; l < NLc; ++l) {
        __half* base = wT + (size_t)l * LWT;
        ln_kernel<<<Mrows, 256>>>(x, ln1_g + (size_t)l*Hc, ln1_b + (size_t)l*Hc, h);
        gemm_h<false,false,true,true><<<qkvTiles, 256, GEMM_SMEM>>>(
            h, base + oQKV_, bqkv + (size_t)l*3*Hc, qkvh, 3*Hc, Hc, 24, qkvTiles);
        flash_kernel<<<dim3(Sc/128, Bc*NHc), 256>>>(qkvh, sp, attn);
        gemm_h<true,false,true,false><<<512, 256, GEMM_SMEM>>>(
            attn, base + oWO_, bo + (size_t)l*Hc, x, Hc, Hc, 8, 512);
        ln_kernel<<<Mrows, 256>>>(x, ln2_g + (size_t)l*Hc, ln2_b + (size_t)l*Hc, h);
        gemm_h<false,true,true,true><<<fcTiles, 256, GEMM_SMEM>>>(
            h, base + oFC_, bfc + (size_t)l*Fc, ffn, Fc, Hc, 32, fcTiles);
        gemm_h<true,false,true,false><<<512, 256, GEMM_SMEM>>>(
            ffn, base + oPRJ_, bproj + (size_t)l*Hc, x, Hc, Fc, 8, 512);
    }

    ln_kernel<<<Mrows, 256>>>(x, lnf_g, lnf_b, h);
    gemm_h<false,false,false,false><<<256, 256, GEMM_SMEM>>>(
        h, embH, nullptr, out, Vc, Hc, 4, 256);
}

// round 14
// speedup vs baseline: 1.5355x; 1.5355x over previous
#include <cuda_runtime.h>
#include <cuda_fp16.h>
#include <math.h>
#include <stdint.h>

// Problem constants
#define Bc   16
#define Sc   512
#define Vc   512
#define Hc   1024
#define NLc  8
#define NHc  16
#define DHc  64
#define Fc   4096
#define Mrows (Bc*Sc)   // 8192 token rows

// per-layer transposed-weight block offsets (element counts)
#define oQKV_ 0
#define oWO_  (3*Hc*Hc)
#define oFC_  (oWO_ + Hc*Hc)
#define oPRJ_ (oFC_ + Hc*Fc)
#define LWT   ((size_t)(oPRJ_ + Fc*Hc))

// ---------------- scratch (static device memory; no runtime allocs) ----------------
__device__ float  g_x   [(size_t)Mrows*Hc];        // residual stream (fp32)
__device__ __half g_h   [(size_t)Mrows*Hc];        // LN output (half)
__device__ __half g_qkvh[(size_t)Mrows*3*Hc];      // fused qkv (half)
__device__ __half g_attn[(size_t)Mrows*Hc];        // attention out (half)
__device__ __half g_ffn [(size_t)Mrows*Fc];        // ffn intermediate (half)
__device__ __half g_wT  [(size_t)NLc * LWT];       // transposed half weights
__device__ __half g_embH[(size_t)Vc*Hc];           // half emb ([V,H] == [N,K] for logits)

// ---------------- helpers ----------------
__device__ __forceinline__ float gelu_f(float x) {
    // tanh-approx gelu, with tanh(u) = 1 - 2/(e^{2u}+1) via fast exp (err ~1e-7)
    float u = 0.7978845608028654f * (x + 0.044715f * x * x * x);
    float t = 1.0f - 2.0f / (__expf(2.0f * u) + 1.0f);
    return 0.5f * x * (1.0f + t);
}
__device__ __forceinline__ void cp16(uint32_t saddr, const void* gptr) {
    asm volatile("cp.async.cg.shared.global [%0], [%1], 16;\n" :: "r"(saddr), "l"(gptr));
}
#define CP_COMMIT() asm volatile("cp.async.commit_group;\n" ::: "memory")
#define CP_WAIT1()  asm volatile("cp.async.wait_group 1;\n" ::: "memory")
#define CP_WAIT0()  asm volatile("cp.async.wait_group 0;\n" ::: "memory")

__device__ __forceinline__ void ldm_x4(uint32_t r[4], uint32_t addr) {
    asm volatile("ldmatrix.sync.aligned.m8n8.x4.shared.b16 {%0,%1,%2,%3}, [%4];"
                 : "=r"(r[0]), "=r"(r[1]), "=r"(r[2]), "=r"(r[3]) : "r"(addr));
}
__device__ __forceinline__ void ldm_x4_t(uint32_t r[4], uint32_t addr) {
    asm volatile("ldmatrix.sync.aligned.m8n8.x4.trans.shared.b16 {%0,%1,%2,%3}, [%4];"
                 : "=r"(r[0]), "=r"(r[1]), "=r"(r[2]), "=r"(r[3]) : "r"(addr));
}
__device__ __forceinline__ void mma_f16(float c[4], const uint32_t a[4],
                                        uint32_t b0, uint32_t b1) {
    asm volatile(
        "mma.sync.aligned.m16n8k16.row.col.f32.f16.f16.f32 "
        "{%0,%1,%2,%3}, {%4,%5,%6,%7}, {%8,%9}, {%0,%1,%2,%3};"
        : "+f"(c[0]), "+f"(c[1]), "+f"(c[2]), "+f"(c[3])
        : "r"(a[0]), "r"(a[1]), "r"(a[2]), "r"(a[3]), "r"(b0), "r"(b1));
}
__device__ __forceinline__ uint32_t pack_h2(float a, float b) {
    __half2 h = __floats2half2_rn(a, b);
    return *(uint32_t*)&h;
}

// ---------------- batched prep: all weight transposes in ONE launch ----------------
// per layer: qkv 3072 tiles | wo 1024 | wfc 4096 | wproj 4096  => 12288/layer
__global__ void prep_weights(const float* __restrict__ Wqkv, const float* __restrict__ Wo,
                             const float* __restrict__ Wfc,  const float* __restrict__ Wproj,
                             __half* __restrict__ wT) {
    __shared__ float t[32][33];
    int bid = blockIdx.x;
    int l = bid / 12288;
    int r = bid % 12288;
    __half* base = wT + (size_t)l * LWT;
    const float* in; __half* outp; int K, N, tn, tk;
    if (r < 3072) {
        in = Wqkv + (size_t)l*Hc*3*Hc; outp = base + oQKV_; K = Hc; N = 3*Hc;
        tn = r % 96; tk = r / 96;
    } else if (r < 4096) {
        int q = r - 3072;
        in = Wo + (size_t)l*Hc*Hc; outp = base + oWO_; K = Hc; N = Hc;
        tn = q % 32; tk = q / 32;
    } else if (r < 8192) {
        int q = r - 4096;
        in = Wfc + (size_t)l*Hc*Fc; outp = base + oFC_; K = Hc; N = Fc;
        tn = q % 128; tk = q / 128;
    } else {
        int q = r - 8192;
        in = Wproj + (size_t)l*Fc*Hc; outp = base + oPRJ_; K = Fc; N = Hc;
        tn = q % 32; tk = q / 32;
    }
    int n0 = tn * 32, k0 = tk * 32;
    int tx = threadIdx.x, ty = threadIdx.y;  // (32,8)
    #pragma unroll
    for (int rr = 0; rr < 32; rr += 8)
        t[ty + rr][tx] = in[(size_t)(k0 + ty + rr) * N + n0 + tx];
    __syncthreads();
    #pragma unroll
    for (int rr = 0; rr < 32; rr += 8)
        outp[(size_t)(n0 + ty + rr) * K + k0 + tx] = __float2half_rn(t[tx][ty + rr]);
}

// embH copy (blocks 0..511) + embedding gather (blocks 512..8703)
__global__ void prep_misc(const float* __restrict__ emb, __half* __restrict__ embH,
                          const int* __restrict__ ids, float* __restrict__ x) {
    int bid = blockIdx.x;
    if (bid < 512) {
        int i = bid * 256 + threadIdx.x;   // float4 index; 512*256 = 131072 = Vc*Hc/4
        float4 v = ((const float4*)emb)[i];
        ((__half2*)embH)[2*i]   = __floats2half2_rn(v.x, v.y);
        ((__half2*)embH)[2*i+1] = __floats2half2_rn(v.z, v.w);
    } else {
        int t = bid - 512;
        int id = ids[t];
        const float4* src = (const float4*)(emb + (size_t)id * Hc);
        float4* dst = (float4*)(x + (size_t)t * Hc);
        dst[threadIdx.x] = src[threadIdx.x];
    }
}

// ---------------- layernorm (half output), warp-shuffle reduce, 1 barrier ----------
__global__ void ln_kernel(const float* __restrict__ x,
                          const float* __restrict__ g,
                          const float* __restrict__ b,
                          __half* __restrict__ out) {
    __shared__ float ws[8], wq[8];
    int row = blockIdx.x, tid = threadIdx.x;
    int lane = tid & 31, w = tid >> 5;
    float4 v = ((const float4*)(x + (size_t)row * Hc))[tid];
    float s = v.x + v.y + v.z + v.w;
    float q = v.x*v.x + v.y*v.y + v.z*v.z + v.w*v.w;
    #pragma unroll
    for (int o = 16; o; o >>= 1) {
        s += __shfl_xor_sync(0xffffffffu, s, o);
        q += __shfl_xor_sync(0xffffffffu, q, o);
    }
    if (lane == 0) { ws[w] = s; wq[w] = q; }
    __syncthreads();
    s = ws[lane & 7]; q = wq[lane & 7];
    #pragma unroll
    for (int o = 4; o; o >>= 1) {
        s += __shfl_xor_sync(0xffffffffu, s, o);
        q += __shfl_xor_sync(0xffffffffu, q, o);
    }
    float mu  = s * (1.0f / Hc);
    float var = q * (1.0f / Hc) - mu * mu;
    float inv = rsqrtf(var + 1e-5f);
    float4 gg = ((const float4*)g)[tid];
    float4 bb = ((const float4*)b)[tid];
    __half2* op = (__half2*)(out + (size_t)row * Hc);
    op[2*tid]   = __floats2half2_rn((v.x - mu) * inv * gg.x + bb.x,
                                    (v.y - mu) * inv * gg.y + bb.y);
    op[2*tid+1] = __floats2half2_rn((v.z - mu) * inv * gg.z + bb.z,
                                    (v.w - mu) * inv * gg.w + bb.w);
}

// ---------------- fp16 tensor-core GEMM: C = act(A@Wt^T + bias) (+= residual C) ------
// R10-proven mainloop (frozen): 3-stage cp.async (96KB), single barrier per K-iter.
// 1D grid + tile loop (grid == nTiles in practice -> single pass).
template<bool RES, bool GELU_ACT, bool BIAS, bool OUT_HALF>
__global__ __launch_bounds__(256, 2)
void gemm_h(const __half* __restrict__ A, const __half* __restrict__ Wt,
            const float* __restrict__ bias, void* __restrict__ Cv,
            int N, int K, int nNt, int nTiles) {
    extern __shared__ uint8_t dsm[];
    uint32_t smem = (uint32_t)__cvta_generic_to_shared(dsm);
    const uint32_t sA = smem;            // 3 stages x 16KB
    const uint32_t sB = smem + 49152;    // 3 stages x 16KB

    int tid = threadIdx.x, wid = tid >> 5, lane = tid & 31;
    int warpM = (wid >> 2) * 64;
    int warpN = (wid & 3) * 32;
    int nIter = K >> 6;

    int row = tid >> 1;
    int hseg = (tid & 1) * 32;
    uint32_t so[4];
    #pragma unroll
    for (int i = 0; i < 4; ++i) {
        int c = (tid & 1) * 4 + i;
        so[i] = row * 128 + ((c ^ (row & 7)) << 4);
    }
    int lrow = lane & 15;
    int lchk = lane >> 4;

    for (int t = blockIdx.x; t < nTiles; t += gridDim.x) {
        if (t != (int)blockIdx.x) __syncthreads();   // prior tile's smem reads done
        int m0 = (t / nNt) * 128, n0 = (t % nNt) * 128;

        float acc[4][4][4];
        #pragma unroll
        for (int i = 0; i < 4; ++i)
            #pragma unroll
            for (int j = 0; j < 4; ++j)
                #pragma unroll
                for (int r = 0; r < 4; ++r) acc[i][j][r] = 0.f;

        const __half* ag = A  + (size_t)(m0 + row) * K + hseg;
        const __half* bg = Wt + (size_t)(n0 + row) * K + hseg;

        auto prefetch = [&](int it) {
            if (it < nIter) {
                uint32_t a_st = sA + (it % 3) * 16384;
                uint32_t b_st = sB + (it % 3) * 16384;
                const __half* ap = ag + (size_t)it * 64;
                const __half* bp = bg + (size_t)it * 64;
                #pragma unroll
                for (int i = 0; i < 4; ++i) cp16(a_st + so[i], ap + 8 * i);
                #pragma unroll
                for (int i = 0; i < 4; ++i) cp16(b_st + so[i], bp + 8 * i);
            }
            CP_COMMIT();
        };

        prefetch(0);
        prefetch(1);

        for (int it = 0; it < nIter; ++it) {
            CP_WAIT1();
            __syncthreads();
            prefetch(it + 2);     // stage (it-1)%3 — free after the barrier
            uint32_t aBase = sA + (it % 3) * 16384;
            uint32_t bBase = sB + (it % 3) * 16384;
            #pragma unroll
            for (int ks = 0; ks < 4; ++ks) {
                uint32_t af[4][4], bf[2][4];
                int c = ks * 2 + lchk;
                #pragma unroll
                for (int mf = 0; mf < 4; ++mf) {
                    int r = warpM + mf * 16 + lrow;
                    ldm_x4(af[mf], aBase + r * 128 + ((c ^ (r & 7)) << 4));
                }
                #pragma unroll
                for (int g = 0; g < 2; ++g) {
                    int r = warpN + g * 16 + lrow;
                    ldm_x4(bf[g], bBase + r * 128 + ((c ^ (r & 7)) << 4));
                }
                #pragma unroll
                for (int mf = 0; mf < 4; ++mf) {
                    mma_f16(acc[mf][0], af[mf], bf[0][0], bf[0][2]);
                    mma_f16(acc[mf][1], af[mf], bf[0][1], bf[0][3]);
                    mma_f16(acc[mf][2], af[mf], bf[1][0], bf[1][2]);
                    mma_f16(acc[mf][3], af[mf], bf[1][1], bf[1][3]);
                }
            }
        }

        int rbase = m0 + warpM + (lane >> 2);
        int cbase = n0 + warpN + (lane & 3) * 2;
        #pragma unroll
        for (int mf = 0; mf < 4; ++mf) {
            #pragma unroll
            for (int nf = 0; nf < 4; ++nf) {
                int c = cbase + nf * 8;
                float bx = 0.f, by = 0.f;
                if (BIAS) { bx = bias[c]; by = bias[c + 1]; }
                #pragma unroll
                for (int half_ = 0; half_ < 2; ++half_) {
                    int r = rbase + mf * 16 + half_ * 8;
                    float v0 = acc[mf][nf][half_ * 2 + 0] + bx;
                    float v1 = acc[mf][nf][half_ * 2 + 1] + by;
                    if (GELU_ACT) { v0 = gelu_f(v0); v1 = gelu_f(v1); }
                    if (OUT_HALF) {
                        __half2* cp = (__half2*)((__half*)Cv + (size_t)r * N + c);
                        *cp = __floats2half2_rn(v0, v1);
                    } else {
                        float2* cp = (float2*)((float*)Cv + (size_t)r * N + c);
                        if (RES) { float2 old = *cp; v0 += old.x; v1 += old.y; }
                        float2 o; o.x = v0; o.y = v1;
                        *cp = o;
                    }
                }
            }
        }
    }
}

// ---------------- fused flash attention ----------------
// grid: (S/128, B*NH); 256 threads (8 warps x 16 rows). K/V 64-row tiles,
// double buffered, single barrier per j-tile, split-mask tile skipping,
// heavy-first (LPT) CTA ordering.
__global__ __launch_bounds__(256)
void flash_kernel(const __half* __restrict__ qkvh, const int* __restrict__ sp,
                  __half* __restrict__ out) {
    __shared__ __align__(128) uint8_t sm[49152];
    uint32_t S0 = (uint32_t)__cvta_generic_to_shared(sm);
    const uint32_t sQ = S0;
    int tid = threadIdx.x, w = tid >> 5, lane = tid & 31;
    int ixt = gridDim.x - 1 - blockIdx.x;       // heavy-first remap
    int i0 = ixt * 128;
    int bz = blockIdx.y;
    int b = bz >> 4, n = bz & 15;
    int spb = sp[b];
    float slope = exp2f(-0.5f * (float)(n + 1));

    const __half* qbase = qkvh + (size_t)b * Sc * 3 * Hc + n * 64;

    int jstart = (spb <= i0) ? (spb >> 6) : 0;

    // Q tile 128x64 -> smem (group 0, together with KV tile jstart)
    #pragma unroll
    for (int itr = 0; itr < 4; ++itr) {
        int id = itr * 256 + tid;
        int row = id >> 3, ch = id & 7;
        cp16(sQ + row * 128 + ((ch ^ (row & 7)) << 4),
             qbase + (size_t)(i0 + row) * 3 * Hc + ch * 8);
    }
    auto prefKV = [&](int jt) {
        int stage = jt & 1;
        uint32_t sK = S0 + 16384 + stage * 16384;
        uint32_t sV = sK + 8192;
        int j0 = jt * 64;
        #pragma unroll
        for (int itr = 0; itr < 2; ++itr) {
            int id = itr * 256 + tid;
            int row = id >> 3, ch = id & 7;
            uint32_t sw = row * 128 + ((ch ^ (row & 7)) << 4);
            const __half* g = qbase + (size_t)(j0 + row) * 3 * Hc + ch * 8;
            cp16(sK + sw, g + Hc);
            cp16(sV + sw, g + 2 * Hc);
        }
    };
    prefKV(jstart);
    CP_COMMIT();

    int jtmax = ixt * 2 + 1;
    int ibase = i0 + w * 16;
    int irow = ibase + (lane >> 2);
    int jcl = (lane & 3) * 2;

    float m_run[2] = {-1e30f, -1e30f};
    float l[2] = {0.f, 0.f};
    float co[8][4];
    #pragma unroll
    for (int i = 0; i < 8; ++i)
        #pragma unroll
        for (int j = 0; j < 4; ++j) co[i][j] = 0.f;
    uint32_t aq[4][4];
    bool qLoaded = false;

    for (int jt = jstart; jt <= jtmax; ++jt) {
        CP_WAIT0();           // stage jt (and everything earlier) resident
        __syncthreads();      // all warps done with compute(jt-1); stage (jt+1)&1 free
        if (jt < jtmax) { prefKV(jt + 1); CP_COMMIT(); }
        int stage = jt & 1;
        uint32_t sK = S0 + 16384 + stage * 16384;
        uint32_t sV = sK + 8192;
        if (!qLoaded) {
            qLoaded = true;
            #pragma unroll
            for (int kc = 0; kc < 4; ++kc) {
                int r = w * 16 + (lane & 15);
                int c = kc * 2 + (lane >> 4);
                ldm_x4(aq[kc], sQ + r * 128 + ((c ^ (r & 7)) << 4));
            }
        }
        int j0 = jt * 64;
        if (j0 <= ibase + 15) {
            float c[8][4];
            #pragma unroll
            for (int i = 0; i < 8; ++i)
                #pragma unroll
                for (int j = 0; j < 4; ++j) c[i][j] = 0.f;
            // S = Q K^T
            #pragma unroll
            for (int kc = 0; kc < 4; ++kc) {
                uint32_t bf[4][4];
                #pragma unroll
                for (int g = 0; g < 4; ++g) {
                    int r = g * 16 + (lane & 15);
                    int cc = kc * 2 + (lane >> 4);
                    ldm_x4(bf[g], sK + r * 128 + ((cc ^ (r & 7)) << 4));
                }
                #pragma unroll
                for (int g = 0; g < 4; ++g) {
                    mma_f16(c[g * 2],     aq[kc], bf[g][0], bf[g][2]);
                    mma_f16(c[g * 2 + 1], aq[kc], bf[g][1], bf[g][3]);
                }
            }
            // mask + alibi
            float tmax[2] = {-1e30f, -1e30f};
            #pragma unroll
            for (int nf = 0; nf < 8; ++nf)
                #pragma unroll
                for (int rg = 0; rg < 4; ++rg) {
                    int i = irow + (rg >> 1) * 8;
                    int j = j0 + nf * 8 + jcl + (rg & 1);
                    bool ok = (j <= i) && !((i >= spb) && (j < spb));
                    float v = ok ? fmaf(c[nf][rg], 0.125f, -slope * (float)(i - j))
                                 : -1e9f;
                    c[nf][rg] = v;
                    tmax[rg >> 1] = fmaxf(tmax[rg >> 1], v);
                }
            float sfv[2];
            #pragma unroll
            for (int h = 0; h < 2; ++h) {
                tmax[h] = fmaxf(tmax[h], __shfl_xor_sync(0xffffffffu, tmax[h], 1));
                tmax[h] = fmaxf(tmax[h], __shfl_xor_sync(0xffffffffu, tmax[h], 2));
                float mn = fmaxf(m_run[h], tmax[h]);
                sfv[h] = __expf(m_run[h] - mn);
                m_run[h] = mn;
            }
            float rs[2] = {0.f, 0.f};
            #pragma unroll
            for (int nf = 0; nf < 8; ++nf)
                #pragma unroll
                for (int rg = 0; rg < 4; ++rg) {
                    float p = __expf(c[nf][rg] - m_run[rg >> 1]);
                    c[nf][rg] = p;
                    rs[rg >> 1] += p;
                }
            #pragma unroll
            for (int h = 0; h < 2; ++h) {
                rs[h] += __shfl_xor_sync(0xffffffffu, rs[h], 1);
                rs[h] += __shfl_xor_sync(0xffffffffu, rs[h], 2);
                l[h] = l[h] * sfv[h] + rs[h];
            }
            #pragma unroll
            for (int nf = 0; nf < 8; ++nf)
                #pragma unroll
                for (int rg = 0; rg < 4; ++rg) co[nf][rg] *= sfv[rg >> 1];
            // P fragments (register reshuffle)
            uint32_t ap[4][4];
            #pragma unroll
            for (int kc = 0; kc < 4; ++kc) {
                ap[kc][0] = pack_h2(c[2*kc][0],   c[2*kc][1]);
                ap[kc][1] = pack_h2(c[2*kc][2],   c[2*kc][3]);
                ap[kc][2] = pack_h2(c[2*kc+1][0], c[2*kc+1][1]);
                ap[kc][3] = pack_h2(c[2*kc+1][2], c[2*kc+1][3]);
            }
            // O += P V
            #pragma unroll
            for (int kc = 0; kc < 4; ++kc) {
                #pragma unroll
                for (int dp = 0; dp < 4; ++dp) {
                    uint32_t vf[4];
                    int r = kc * 16 + (lane & 15);
                    int cc = dp * 2 + (lane >> 4);
                    ldm_x4_t(vf, sV + r * 128 + ((cc ^ (r & 7)) << 4));
                    mma_f16(co[dp * 2],     ap[kc], vf[0], vf[1]);
                    mma_f16(co[dp * 2 + 1], ap[kc], vf[2], vf[3]);
                }
            }
        }
    }

    float inv0 = 1.0f / l[0], inv1 = 1.0f / l[1];
    #pragma unroll
    for (int nf = 0; nf < 8; ++nf) {
        int cidx = n * 64 + nf * 8 + jcl;
        __half2* o0 = (__half2*)&out[(size_t)(b * Sc + irow) * Hc + cidx];
        *o0 = __floats2half2_rn(co[nf][0] * inv0, co[nf][1] * inv0);
        __half2* o1 = (__half2*)&out[(size_t)(b * Sc + irow + 8) * Hc + cidx];
        *o1 = __floats2half2_rn(co[nf][2] * inv1, co[nf][3] * inv1);
    }
}

// ---------------- launch ----------------
#define GEMM_SMEM 98304

extern "C" void kernel_launch(void* const* d_in, const int* in_sizes, int n_in,
                              void* d_out, int out_size) {
    const int*   ids    = (const int*)d_in[0];
    const int*   sp     = (const int*)d_in[1];
    const float* emb    = (const float*)d_in[2];
    const float* ln1_g  = (const float*)d_in[3];
    const float* ln1_b  = (const float*)d_in[4];
    const float* Wqkv   = (const float*)d_in[5];
    const float* bqkv   = (const float*)d_in[6];
    const float* Wo     = (const float*)d_in[7];
    const float* bo     = (const float*)d_in[8];
    const float* ln2_g  = (const float*)d_in[9];
    const float* ln2_b  = (const float*)d_in[10];
    const float* Wfc    = (const float*)d_in[11];
    const float* bfc    = (const float*)d_in[12];
    const float* Wproj  = (const float*)d_in[13];
    const float* bproj  = (const float*)d_in[14];
    const float* lnf_g  = (const float*)d_in[15];
    const float* lnf_b  = (const float*)d_in[16];
    float* out = (float*)d_out;

    float *x;
    __half *h, *qkvh, *attn, *ffn, *wT, *embH;
    cudaGetSymbolAddress((void**)&x,    g_x);
    cudaGetSymbolAddress((void**)&h,    g_h);
    cudaGetSymbolAddress((void**)&qkvh, g_qkvh);
    cudaGetSymbolAddress((void**)&attn, g_attn);
    cudaGetSymbolAddress((void**)&ffn,  g_ffn);
    cudaGetSymbolAddress((void**)&wT,   g_wT);
    cudaGetSymbolAddress((void**)&embH, g_embH);

    cudaFuncSetAttribute(gemm_h<false,false,true,true>,
                         cudaFuncAttributeMaxDynamicSharedMemorySize, GEMM_SMEM);
    cudaFuncSetAttribute(gemm_h<true,false,true,false>,
                         cudaFuncAttributeMaxDynamicSharedMemorySize, GEMM_SMEM);
    cudaFuncSetAttribute(gemm_h<false,true,true,true>,
                         cudaFuncAttributeMaxDynamicSharedMemorySize, GEMM_SMEM);
    cudaFuncSetAttribute(gemm_h<false,false,false,false>,
                         cudaFuncAttributeMaxDynamicSharedMemorySize, GEMM_SMEM);

    prep_weights<<<NLc * 12288, dim3(32, 8)>>>(Wqkv, Wo, Wfc, Wproj, wT);
    prep_misc<<<512 + Mrows, 256>>>(emb, embH, ids, x);

    const int qkvTiles = (3*Hc/128) * (Mrows/128);     // 1536
    const int fcTiles  = (Fc/128) * (Mrows/128);       // 2048

    for (int l = 0; l < NLc; ++l) {
        __half* base = wT + (size_t)l * LWT;
        ln_kernel<<<Mrows, 256>>>(x, ln1_g + (size_t)l*Hc, ln1_b + (size_t)l*Hc, h);
        gemm_h<false,false,true,true><<<qkvTiles, 256, GEMM_SMEM>>>(
            h, base + oQKV_, bqkv + (size_t)l*3*Hc, qkvh, 3*Hc, Hc, 24, qkvTiles);
        flash_kernel<<<dim3(Sc/128, Bc*NHc), 256>>>(qkvh, sp, attn);
        gemm_h<true,false,true,false><<<512, 256, GEMM_SMEM>>>(
            attn, base + oWO_, bo + (size_t)l*Hc, x, Hc, Hc, 8, 512);
        ln_kernel<<<Mrows, 256>>>(x, ln2_g + (size_t)l*Hc, ln2_b + (size_t)l*Hc, h);
        gemm_h<false,true,true,true><<<fcTiles, 256, GEMM_SMEM>>>(
            h, base + oFC_, bfc + (size_t)l*Fc, ffn, Fc, Hc, 32, fcTiles);
        gemm_h<true,false,true,false><<<512, 256, GEMM_SMEM>>>(
            ffn, base + oPRJ_, bproj + (size_t)l*Hc, x, Hc, Fc, 8, 512);
    }

    ln_kernel<<<Mrows, 256>>>(x, lnf_g, lnf_b, h);
    gemm_h<false,false,false,false><<<256, 256, GEMM_SMEM>>>(
        h, embH, nullptr, out, Vc, Hc, 4, 256);
}

// round 15
// speedup vs baseline: 1.5982x; 1.0408x over previous
#include <cuda_runtime.h>
#include <cuda_fp16.h>
#include <math.h>
#include <stdint.h>

// Problem constants
#define Bc   16
#define Sc   512
#define Vc   512
#define Hc   1024
#define NLc  8
#define NHc  16
#define DHc  64
#define Fc   4096
#define Mrows (Bc*Sc)   // 8192 token rows

// per-layer transposed-weight block offsets (element counts)
#define oQKV_ 0
#define oWO_  (3*Hc*Hc)
#define oFC_  (oWO_ + Hc*Hc)
#define oPRJ_ (oFC_ + Hc*Fc)
#define LWT   ((size_t)(oPRJ_ + Fc*Hc))

// ---------------- scratch (static device memory; no runtime allocs) ----------------
__device__ float  g_x   [(size_t)Mrows*Hc];        // residual stream (fp32)
__device__ __half g_h   [(size_t)Mrows*Hc];        // LN output (half)
__device__ __half g_qkvh[(size_t)Mrows*3*Hc];      // fused qkv (half)
__device__ __half g_attn[(size_t)Mrows*Hc];        // attention out (half)
__device__ __half g_ffn [(size_t)Mrows*Fc];        // ffn intermediate (half)
__device__ __half g_wT  [(size_t)NLc * LWT];       // transposed half weights
__device__ __half g_embH[(size_t)Vc*Hc];           // half emb ([V,H] == [N,K] for logits)

// ---------------- helpers ----------------
__device__ __forceinline__ float gelu_f(float x) {
    float u = 0.7978845608028654f * (x + 0.044715f * x * x * x);
    float t = 1.0f - 2.0f / (__expf(2.0f * u) + 1.0f);
    return 0.5f * x * (1.0f + t);
}
__device__ __forceinline__ void cp16(uint32_t saddr, const void* gptr) {
    asm volatile("cp.async.cg.shared.global [%0], [%1], 16;\n" :: "r"(saddr), "l"(gptr));
}
#define CP_COMMIT() asm volatile("cp.async.commit_group;\n" ::: "memory")
#define CP_WAIT1()  asm volatile("cp.async.wait_group 1;\n" ::: "memory")
#define CP_WAIT0()  asm volatile("cp.async.wait_group 0;\n" ::: "memory")

__device__ __forceinline__ void ldm_x4(uint32_t r[4], uint32_t addr) {
    asm volatile("ldmatrix.sync.aligned.m8n8.x4.shared.b16 {%0,%1,%2,%3}, [%4];"
                 : "=r"(r[0]), "=r"(r[1]), "=r"(r[2]), "=r"(r[3]) : "r"(addr));
}
__device__ __forceinline__ void ldm_x4_t(uint32_t r[4], uint32_t addr) {
    asm volatile("ldmatrix.sync.aligned.m8n8.x4.trans.shared.b16 {%0,%1,%2,%3}, [%4];"
                 : "=r"(r[0]), "=r"(r[1]), "=r"(r[2]), "=r"(r[3]) : "r"(addr));
}
__device__ __forceinline__ void mma_f16(float c[4], const uint32_t a[4],
                                        uint32_t b0, uint32_t b1) {
    asm volatile(
        "mma.sync.aligned.m16n8k16.row.col.f32.f16.f16.f32 "
        "{%0,%1,%2,%3}, {%4,%5,%6,%7}, {%8,%9}, {%0,%1,%2,%3};"
        : "+f"(c[0]), "+f"(c[1]), "+f"(c[2]), "+f"(c[3])
        : "r"(a[0]), "r"(a[1]), "r"(a[2]), "r"(a[3]), "r"(b0), "r"(b1));
}
__device__ __forceinline__ uint32_t pack_h2(float a, float b) {
    __half2 h = __floats2half2_rn(a, b);
    return *(uint32_t*)&h;
}

// ---------------- batched prep: all weight transposes in ONE launch ----------------
__global__ void prep_weights(const float* __restrict__ Wqkv, const float* __restrict__ Wo,
                             const float* __restrict__ Wfc,  const float* __restrict__ Wproj,
                             __half* __restrict__ wT) {
    __shared__ float t[32][33];
    int bid = blockIdx.x;
    int l = bid / 12288;
    int r = bid % 12288;
    __half* base = wT + (size_t)l * LWT;
    const float* in; __half* outp; int K, N, tn, tk;
    if (r < 3072) {
        in = Wqkv + (size_t)l*Hc*3*Hc; outp = base + oQKV_; K = Hc; N = 3*Hc;
        tn = r % 96; tk = r / 96;
    } else if (r < 4096) {
        int q = r - 3072;
        in = Wo + (size_t)l*Hc*Hc; outp = base + oWO_; K = Hc; N = Hc;
        tn = q % 32; tk = q / 32;
    } else if (r < 8192) {
        int q = r - 4096;
        in = Wfc + (size_t)l*Hc*Fc; outp = base + oFC_; K = Hc; N = Fc;
        tn = q % 128; tk = q / 128;
    } else {
        int q = r - 8192;
        in = Wproj + (size_t)l*Fc*Hc; outp = base + oPRJ_; K = Fc; N = Hc;
        tn = q % 32; tk = q / 32;
    }
    int n0 = tn * 32, k0 = tk * 32;
    int tx = threadIdx.x, ty = threadIdx.y;  // (32,8)
    #pragma unroll
    for (int rr = 0; rr < 32; rr += 8)
        t[ty + rr][tx] = in[(size_t)(k0 + ty + rr) * N + n0 + tx];
    __syncthreads();
    #pragma unroll
    for (int rr = 0; rr < 32; rr += 8)
        outp[(size_t)(n0 + ty + rr) * K + k0 + tx] = __float2half_rn(t[tx][ty + rr]);
}

// embH copy (blocks 0..511) + embedding gather (blocks 512..8703)
__global__ void prep_misc(const float* __restrict__ emb, __half* __restrict__ embH,
                          const int* __restrict__ ids, float* __restrict__ x) {
    int bid = blockIdx.x;
    if (bid < 512) {
        int i = bid * 256 + threadIdx.x;
        float4 v = ((const float4*)emb)[i];
        ((__half2*)embH)[2*i]   = __floats2half2_rn(v.x, v.y);
        ((__half2*)embH)[2*i+1] = __floats2half2_rn(v.z, v.w);
    } else {
        int t = bid - 512;
        int id = ids[t];
        const float4* src = (const float4*)(emb + (size_t)id * Hc);
        float4* dst = (float4*)(x + (size_t)t * Hc);
        dst[threadIdx.x] = src[threadIdx.x];
    }
}

// ---------------- layernorm (half output), warp-shuffle reduce, 1 barrier ----------
__global__ void ln_kernel(const float* __restrict__ x,
                          const float* __restrict__ g,
                          const float* __restrict__ b,
                          __half* __restrict__ out) {
    __shared__ float ws[8], wq[8];
    int row = blockIdx.x, tid = threadIdx.x;
    int lane = tid & 31, w = tid >> 5;
    float4 v = ((const float4*)(x + (size_t)row * Hc))[tid];
    float s = v.x + v.y + v.z + v.w;
    float q = v.x*v.x + v.y*v.y + v.z*v.z + v.w*v.w;
    #pragma unroll
    for (int o = 16; o; o >>= 1) {
        s += __shfl_xor_sync(0xffffffffu, s, o);
        q += __shfl_xor_sync(0xffffffffu, q, o);
    }
    if (lane == 0) { ws[w] = s; wq[w] = q; }
    __syncthreads();
    s = ws[lane & 7]; q = wq[lane & 7];
    #pragma unroll
    for (int o = 4; o; o >>= 1) {
        s += __shfl_xor_sync(0xffffffffu, s, o);
        q += __shfl_xor_sync(0xffffffffu, q, o);
    }
    float mu  = s * (1.0f / Hc);
    float var = q * (1.0f / Hc) - mu * mu;
    float inv = rsqrtf(var + 1e-5f);
    float4 gg = ((const float4*)g)[tid];
    float4 bb = ((const float4*)b)[tid];
    __half2* op = (__half2*)(out + (size_t)row * Hc);
    op[2*tid]   = __floats2half2_rn((v.x - mu) * inv * gg.x + bb.x,
                                    (v.y - mu) * inv * gg.y + bb.y);
    op[2*tid+1] = __floats2half2_rn((v.z - mu) * inv * gg.z + bb.z,
                                    (v.w - mu) * inv * gg.w + bb.w);
}

// ---------------- fp16 tensor-core GEMM: C = act(A@Wt^T + bias) (+= residual C) ------
// NEW geometry: CTA tile 128x64, warp tile 32x32 (8 warps in 4x2), BK=64,
// 3-stage cp.async pipeline (72KB smem) -> 3 CTAs/SM (24 warps, 37.5% occ).
// 32 fp32 accumulators/thread keeps regs under the 84-reg cap without spilling.
// Mainloop protocol identical to the R10-proven one (single barrier per K-iter).
template<bool RES, bool GELU_ACT, bool BIAS, bool OUT_HALF>
__global__ __launch_bounds__(256, 3)
void gemm_h(const __half* __restrict__ A, const __half* __restrict__ Wt,
            const float* __restrict__ bias, void* __restrict__ Cv,
            int N, int K, int nNt, int nTiles) {
    extern __shared__ uint8_t dsm[];
    uint32_t smem = (uint32_t)__cvta_generic_to_shared(dsm);
    const uint32_t sA = smem;            // 3 stages x 16KB
    const uint32_t sB = smem + 49152;    // 3 stages x 8KB

    int tid = threadIdx.x, wid = tid >> 5, lane = tid & 31;
    int warpM = (wid >> 1) * 32;         // 4 warp-rows
    int warpN = (wid & 1) * 32;          // 2 warp-cols
    int nIter = K >> 6;

    // A loads: row 0..127, (tid&1)*32 halves -> 4 cp16
    int arow = tid >> 1;
    int akc  = (tid & 1) * 32;
    uint32_t soA[4];
    #pragma unroll
    for (int i = 0; i < 4; ++i) {
        int c = (tid & 1) * 4 + i;
        soA[i] = arow * 128 + ((c ^ (arow & 7)) << 4);
    }
    // B loads: row 0..63, (tid&3)*16 halves -> 2 cp16
    int brow = tid >> 2;
    int bkc  = (tid & 3) * 16;
    uint32_t soB[2];
    #pragma unroll
    for (int i = 0; i < 2; ++i) {
        int c = (tid & 3) * 2 + i;
        soB[i] = brow * 128 + ((c ^ (brow & 7)) << 4);
    }
    int lrow = lane & 15;
    int lchk = lane >> 4;

    for (int t = blockIdx.x; t < nTiles; t += gridDim.x) {
        if (t != (int)blockIdx.x) __syncthreads();
        int m0 = (t / nNt) * 128, n0 = (t % nNt) * 64;

        float acc[2][4][4];
        #pragma unroll
        for (int i = 0; i < 2; ++i)
            #pragma unroll
            for (int j = 0; j < 4; ++j)
                #pragma unroll
                for (int r = 0; r < 4; ++r) acc[i][j][r] = 0.f;

        const __half* ag = A  + (size_t)(m0 + arow) * K + akc;
        const __half* bg = Wt + (size_t)(n0 + brow) * K + bkc;

        auto prefetch = [&](int it) {
            if (it < nIter) {
                uint32_t a_st = sA + (it % 3) * 16384;
                uint32_t b_st = sB + (it % 3) * 8192;
                const __half* ap = ag + (size_t)it * 64;
                const __half* bp = bg + (size_t)it * 64;
                #pragma unroll
                for (int i = 0; i < 4; ++i) cp16(a_st + soA[i], ap + 8 * i);
                #pragma unroll
                for (int i = 0; i < 2; ++i) cp16(b_st + soB[i], bp + 8 * i);
            }
            CP_COMMIT();
        };

        prefetch(0);
        prefetch(1);

        for (int it = 0; it < nIter; ++it) {
            CP_WAIT1();
            __syncthreads();
            prefetch(it + 2);     // stage (it-1)%3 — free after the barrier
            uint32_t aBase = sA + (it % 3) * 16384;
            uint32_t bBase = sB + (it % 3) * 8192;
            #pragma unroll
            for (int ks = 0; ks < 4; ++ks) {
                uint32_t af[2][4], bf[2][4];
                int c = ks * 2 + lchk;
                #pragma unroll
                for (int mf = 0; mf < 2; ++mf) {
                    int r = warpM + mf * 16 + lrow;
                    ldm_x4(af[mf], aBase + r * 128 + ((c ^ (r & 7)) << 4));
                }
                #pragma unroll
                for (int g = 0; g < 2; ++g) {
                    int r = warpN + g * 16 + lrow;
                    ldm_x4(bf[g], bBase + r * 128 + ((c ^ (r & 7)) << 4));
                }
                #pragma unroll
                for (int mf = 0; mf < 2; ++mf) {
                    mma_f16(acc[mf][0], af[mf], bf[0][0], bf[0][2]);
                    mma_f16(acc[mf][1], af[mf], bf[0][1], bf[0][3]);
                    mma_f16(acc[mf][2], af[mf], bf[1][0], bf[1][2]);
                    mma_f16(acc[mf][3], af[mf], bf[1][1], bf[1][3]);
                }
            }
        }

        int rbase = m0 + warpM + (lane >> 2);
        int cbase = n0 + warpN + (lane & 3) * 2;
        #pragma unroll
        for (int mf = 0; mf < 2; ++mf) {
            #pragma unroll
            for (int nf = 0; nf < 4; ++nf) {
                int c = cbase + nf * 8;
                float bx = 0.f, by = 0.f;
                if (BIAS) { bx = bias[c]; by = bias[c + 1]; }
                #pragma unroll
                for (int half_ = 0; half_ < 2; ++half_) {
                    int r = rbase + mf * 16 + half_ * 8;
                    float v0 = acc[mf][nf][half_ * 2 + 0] + bx;
                    float v1 = acc[mf][nf][half_ * 2 + 1] + by;
                    if (GELU_ACT) { v0 = gelu_f(v0); v1 = gelu_f(v1); }
                    if (OUT_HALF) {
                        __half2* cp = (__half2*)((__half*)Cv + (size_t)r * N + c);
                        *cp = __floats2half2_rn(v0, v1);
                    } else {
                        float2* cp = (float2*)((float*)Cv + (size_t)r * N + c);
                        if (RES) { float2 old = *cp; v0 += old.x; v1 += old.y; }
                        float2 o; o.x = v0; o.y = v1;
                        *cp = o;
                    }
                }
            }
        }
    }
}

// ---------------- fused flash attention ----------------
// grid: (S/128, B*NH); 256 threads (8 warps x 16 rows). K/V 64-row tiles,
// double buffered, single barrier per j-tile, split-mask tile skipping,
// heavy-first (LPT) CTA ordering.
__global__ __launch_bounds__(256)
void flash_kernel(const __half* __restrict__ qkvh, const int* __restrict__ sp,
                  __half* __restrict__ out) {
    __shared__ __align__(128) uint8_t sm[49152];
    uint32_t S0 = (uint32_t)__cvta_generic_to_shared(sm);
    const uint32_t sQ = S0;
    int tid = threadIdx.x, w = tid >> 5, lane = tid & 31;
    int ixt = gridDim.x - 1 - blockIdx.x;       // heavy-first remap
    int i0 = ixt * 128;
    int bz = blockIdx.y;
    int b = bz >> 4, n = bz & 15;
    int spb = sp[b];
    float slope = exp2f(-0.5f * (float)(n + 1));

    const __half* qbase = qkvh + (size_t)b * Sc * 3 * Hc + n * 64;

    int jstart = (spb <= i0) ? (spb >> 6) : 0;

    #pragma unroll
    for (int itr = 0; itr < 4; ++itr) {
        int id = itr * 256 + tid;
        int row = id >> 3, ch = id & 7;
        cp16(sQ + row * 128 + ((ch ^ (row & 7)) << 4),
             qbase + (size_t)(i0 + row) * 3 * Hc + ch * 8);
    }
    auto prefKV = [&](int jt) {
        int stage = jt & 1;
        uint32_t sK = S0 + 16384 + stage * 16384;
        uint32_t sV = sK + 8192;
        int j0 = jt * 64;
        #pragma unroll
        for (int itr = 0; itr < 2; ++itr) {
            int id = itr * 256 + tid;
            int row = id >> 3, ch = id & 7;
            uint32_t sw = row * 128 + ((ch ^ (row & 7)) << 4);
            const __half* g = qbase + (size_t)(j0 + row) * 3 * Hc + ch * 8;
            cp16(sK + sw, g + Hc);
            cp16(sV + sw, g + 2 * Hc);
        }
    };
    prefKV(jstart);
    CP_COMMIT();

    int jtmax = ixt * 2 + 1;
    int ibase = i0 + w * 16;
    int irow = ibase + (lane >> 2);
    int jcl = (lane & 3) * 2;

    float m_run[2] = {-1e30f, -1e30f};
    float l[2] = {0.f, 0.f};
    float co[8][4];
    #pragma unroll
    for (int i = 0; i < 8; ++i)
        #pragma unroll
        for (int j = 0; j < 4; ++j) co[i][j] = 0.f;
    uint32_t aq[4][4];
    bool qLoaded = false;

    for (int jt = jstart; jt <= jtmax; ++jt) {
        CP_WAIT0();
        __syncthreads();
        if (jt < jtmax) { prefKV(jt + 1); CP_COMMIT(); }
        int stage = jt & 1;
        uint32_t sK = S0 + 16384 + stage * 16384;
        uint32_t sV = sK + 8192;
        if (!qLoaded) {
            qLoaded = true;
            #pragma unroll
            for (int kc = 0; kc < 4; ++kc) {
                int r = w * 16 + (lane & 15);
                int c = kc * 2 + (lane >> 4);
                ldm_x4(aq[kc], sQ + r * 128 + ((c ^ (r & 7)) << 4));
            }
        }
        int j0 = jt * 64;
        if (j0 <= ibase + 15) {
            float c[8][4];
            #pragma unroll
            for (int i = 0; i < 8; ++i)
                #pragma unroll
                for (int j = 0; j < 4; ++j) c[i][j] = 0.f;
            #pragma unroll
            for (int kc = 0; kc < 4; ++kc) {
                uint32_t bf[4][4];
                #pragma unroll
                for (int g = 0; g < 4; ++g) {
                    int r = g * 16 + (lane & 15);
                    int cc = kc * 2 + (lane >> 4);
                    ldm_x4(bf[g], sK + r * 128 + ((cc ^ (r & 7)) << 4));
                }
                #pragma unroll
                for (int g = 0; g < 4; ++g) {
                    mma_f16(c[g * 2],     aq[kc], bf[g][0], bf[g][2]);
                    mma_f16(c[g * 2 + 1], aq[kc], bf[g][1], bf[g][3]);
                }
            }
            float tmax[2] = {-1e30f, -1e30f};
            #pragma unroll
            for (int nf = 0; nf < 8; ++nf)
                #pragma unroll
                for (int rg = 0; rg < 4; ++rg) {
                    int i = irow + (rg >> 1) * 8;
                    int j = j0 + nf * 8 + jcl + (rg & 1);
                    bool ok = (j <= i) && !((i >= spb) && (j < spb));
                    float v = ok ? fmaf(c[nf][rg], 0.125f, -slope * (float)(i - j))
                                 : -1e9f;
                    c[nf][rg] = v;
                    tmax[rg >> 1] = fmaxf(tmax[rg >> 1], v);
                }
            float sfv[2];
            #pragma unroll
            for (int h = 0; h < 2; ++h) {
                tmax[h] = fmaxf(tmax[h], __shfl_xor_sync(0xffffffffu, tmax[h], 1));
                tmax[h] = fmaxf(tmax[h], __shfl_xor_sync(0xffffffffu, tmax[h], 2));
                float mn = fmaxf(m_run[h], tmax[h]);
                sfv[h] = __expf(m_run[h] - mn);
                m_run[h] = mn;
            }
            float rs[2] = {0.f, 0.f};
            #pragma unroll
            for (int nf = 0; nf < 8; ++nf)
                #pragma unroll
                for (int rg = 0; rg < 4; ++rg) {
                    float p = __expf(c[nf][rg] - m_run[rg >> 1]);
                    c[nf][rg] = p;
                    rs[rg >> 1] += p;
                }
            #pragma unroll
            for (int h = 0; h < 2; ++h) {
                rs[h] += __shfl_xor_sync(0xffffffffu, rs[h], 1);
                rs[h] += __shfl_xor_sync(0xffffffffu, rs[h], 2);
                l[h] = l[h] * sfv[h] + rs[h];
            }
            #pragma unroll
            for (int nf = 0; nf < 8; ++nf)
                #pragma unroll
                for (int rg = 0; rg < 4; ++rg) co[nf][rg] *= sfv[rg >> 1];
            uint32_t ap[4][4];
            #pragma unroll
            for (int kc = 0; kc < 4; ++kc) {
                ap[kc][0] = pack_h2(c[2*kc][0],   c[2*kc][1]);
                ap[kc][1] = pack_h2(c[2*kc][2],   c[2*kc][3]);
                ap[kc][2] = pack_h2(c[2*kc+1][0], c[2*kc+1][1]);
                ap[kc][3] = pack_h2(c[2*kc+1][2], c[2*kc+1][3]);
            }
            #pragma unroll
            for (int kc = 0; kc < 4; ++kc) {
                #pragma unroll
                for (int dp = 0; dp < 4; ++dp) {
                    uint32_t vf[4];
                    int r = kc * 16 + (lane & 15);
                    int cc = dp * 2 + (lane >> 4);
                    ldm_x4_t(vf, sV + r * 128 + ((cc ^ (r & 7)) << 4));
                    mma_f16(co[dp * 2],     ap[kc], vf[0], vf[1]);
                    mma_f16(co[dp * 2 + 1], ap[kc], vf[2], vf[3]);
                }
            }
        }
    }

    float inv0 = 1.0f / l[0], inv1 = 1.0f / l[1];
    #pragma unroll
    for (int nf = 0; nf < 8; ++nf) {
        int cidx = n * 64 + nf * 8 + jcl;
        __half2* o0 = (__half2*)&out[(size_t)(b * Sc + irow) * Hc + cidx];
        *o0 = __floats2half2_rn(co[nf][0] * inv0, co[nf][1] * inv0);
        __half2* o1 = (__half2*)&out[(size_t)(b * Sc + irow + 8) * Hc + cidx];
        *o1 = __floats2half2_rn(co[nf][2] * inv1, co[nf][3] * inv1);
    }
}

// ---------------- launch ----------------
#define GEMM_SMEM 73728   // 3 stages x (16KB A + 8KB B)

extern "C" void kernel_launch(void* const* d_in, const int* in_sizes, int n_in,
                              void* d_out, int out_size) {
    const int*   ids    = (const int*)d_in[0];
    const int*   sp     = (const int*)d_in[1];
    const float* emb    = (const float*)d_in[2];
    const float* ln1_g  = (const float*)d_in[3];
    const float* ln1_b  = (const float*)d_in[4];
    const float* Wqkv   = (const float*)d_in[5];
    const float* bqkv   = (const float*)d_in[6];
    const float* Wo     = (const float*)d_in[7];
    const float* bo     = (const float*)d_in[8];
    const float* ln2_g  = (const float*)d_in[9];
    const float* ln2_b  = (const float*)d_in[10];
    const float* Wfc    = (const float*)d_in[11];
    const float* bfc    = (const float*)d_in[12];
    const float* Wproj  = (const float*)d_in[13];
    const float* bproj  = (const float*)d_in[14];
    const float* lnf_g  = (const float*)d_in[15];
    const float* lnf_b  = (const float*)d_in[16];
    float* out = (float*)d_out;

    float *x;
    __half *h, *qkvh, *attn, *ffn, *wT, *embH;
    cudaGetSymbolAddress((void**)&x,    g_x);
    cudaGetSymbolAddress((void**)&h,    g_h);
    cudaGetSymbolAddress((void**)&qkvh, g_qkvh);
    cudaGetSymbolAddress((void**)&attn, g_attn);
    cudaGetSymbolAddress((void**)&ffn,  g_ffn);
    cudaGetSymbolAddress((void**)&wT,   g_wT);
    cudaGetSymbolAddress((void**)&embH, g_embH);

    cudaFuncSetAttribute(gemm_h<false,false,true,true>,
                         cudaFuncAttributeMaxDynamicSharedMemorySize, GEMM_SMEM);
    cudaFuncSetAttribute(gemm_h<true,false,true,false>,
                         cudaFuncAttributeMaxDynamicSharedMemorySize, GEMM_SMEM);
    cudaFuncSetAttribute(gemm_h<false,true,true,true>,
                         cudaFuncAttributeMaxDynamicSharedMemorySize, GEMM_SMEM);
    cudaFuncSetAttribute(gemm_h<false,false,false,false>,
                         cudaFuncAttributeMaxDynamicSharedMemorySize, GEMM_SMEM);

    prep_weights<<<NLc * 12288, dim3(32, 8)>>>(Wqkv, Wo, Wfc, Wproj, wT);
    prep_misc<<<512 + Mrows, 256>>>(emb, embH, ids, x);

    // 128x64 tiles: nNt = N/64
    const int qkvTiles = (Mrows/128) * (3*Hc/64);  // 64 x 48 = 3072
    const int woTiles  = (Mrows/128) * (Hc/64);    // 64 x 16 = 1024
    const int fcTiles  = (Mrows/128) * (Fc/64);    // 64 x 64 = 4096
    const int lgTiles  = (Mrows/128) * (Vc/64);    // 64 x 8  = 512

    for (int l = 0; l < NLc; ++l) {
        __half* base = wT + (size_t)l * LWT;
        ln_kernel<<<Mrows, 256>>>(x, ln1_g + (size_t)l*Hc, ln1_b + (size_t)l*Hc, h);
        gemm_h<false,false,true,true><<<qkvTiles, 256, GEMM_SMEM>>>(
            h, base + oQKV_, bqkv + (size_t)l*3*Hc, qkvh, 3*Hc, Hc, 48, qkvTiles);
        flash_kernel<<<dim3(Sc/128, Bc*NHc), 256>>>(qkvh, sp, attn);
        gemm_h<true,false,true,false><<<woTiles, 256, GEMM_SMEM>>>(
            attn, base + oWO_, bo + (size_t)l*Hc, x, Hc, Hc, 16, woTiles);
        ln_kernel<<<Mrows, 256>>>(x, ln2_g + (size_t)l*Hc, ln2_b + (size_t)l*Hc, h);
        gemm_h<false,true,true,true><<<fcTiles, 256, GEMM_SMEM>>>(
            h, base + oFC_, bfc + (size_t)l*Fc, ffn, Fc, Hc, 64, fcTiles);
        gemm_h<true,false,true,false><<<woTiles, 256, GEMM_SMEM>>>(
            ffn, base + oPRJ_, bproj + (size_t)l*Hc, x, Hc, Fc, 16, woTiles);
    }

    ln_kernel<<<Mrows, 256>>>(x, lnf_g, lnf_b, h);
    gemm_h<false,false,false,false><<<lgTiles, 256, GEMM_SMEM>>>(
        h, embH, nullptr, out, Vc, Hc, 8, lgTiles);
}